// round 1
// baseline (speedup 1.0000x reference)
#include <cuda_runtime.h>
#include <math.h>

#define NTOK 1026
#define NPLY 1024
#define HD   128
#define SROW 1032   /* padded score row (16B-aligned rows) */

// ---------------- scratch (static device allocations only) ----------------
__device__ float g_h    [NTOK*HD];
__device__ float g_qkv  [NTOK*3*HD];
__device__ float g_scores[4*NTOK*SROW];
__device__ float g_attn [NTOK*HD];
__device__ float g_h2   [NTOK*HD];
__device__ float g_mem  [NPLY*HD];
__device__ float g_hi   [NPLY*HD];
__device__ float g_hjb  [NPLY*HD];

// ---------------- k1: build x and h = x @ fc_w.T + fc_b -------------------
__global__ void k_embed(const float* __restrict__ env, const float* __restrict__ pf,
                        const float* __restrict__ mw,  const float* __restrict__ lc,
                        const float* __restrict__ wal, const float* __restrict__ fcw,
                        const float* __restrict__ fcb)
{
    int r = blockIdx.x, o = threadIdx.x;
    const float* wrow = fcw + o * 18;
    float acc = fcb[o];
    if (r == 0) {
        #pragma unroll
        for (int t = 0; t < 16; t++) acc += wrow[2 + t] * env[t];
    } else {
        float a, b;
        if (r <= NPLY) { a = lc[r-1]; b = wal[r-1]; }
        else           { a = pf[0];   b = mw[0];    }
        acc += wrow[0]*a + wrow[1]*b;
    }
    g_h[r*HD + o] = acc;
}

// ---------------- k2: qkv = h @ in_w.T + in_b ------------------------------
__global__ void k_qkv(const float* __restrict__ inw, const float* __restrict__ inb)
{
    __shared__ float sh[8][HD];
    int rb  = blockIdx.x * 8;
    int tid = threadIdx.x;                    // 384 threads
    for (int idx = tid; idx < 8*HD; idx += 384) {
        int rr = idx >> 7, k = idx & 127;
        sh[rr][k] = (rb + rr < NTOK) ? g_h[(rb+rr)*HD + k] : 0.f;
    }
    __syncthreads();
    int o = tid;
    float acc[8];
    #pragma unroll
    for (int i = 0; i < 8; i++) acc[i] = inb[o];
    const float4* w4 = (const float4*)(inw + o * HD);
    #pragma unroll 4
    for (int k4 = 0; k4 < 32; k4++) {
        float4 w = w4[k4];
        #pragma unroll
        for (int i = 0; i < 8; i++) {
            acc[i] += sh[i][k4*4+0]*w.x + sh[i][k4*4+1]*w.y
                    + sh[i][k4*4+2]*w.z + sh[i][k4*4+3]*w.w;
        }
    }
    #pragma unroll
    for (int i = 0; i < 8; i++)
        if (rb + i < NTOK) g_qkv[(rb+i)*384 + o] = acc[i];
}

// ---------------- k3: scores = Q K^T / sqrt(32) ----------------------------
__global__ void k_scores()
{
    __shared__ float Qs[32*64];   // [d][q]
    __shared__ float Ks[32*64];   // [d][k]
    int qb = blockIdx.x * 64, kb = blockIdx.y * 64, h = blockIdx.z;
    int tid = threadIdx.x;        // 256
    for (int idx = tid; idx < 2048; idx += 256) {
        int q = idx & 63, d = idx >> 6;
        int gq = qb + q, gk = kb + q;
        Qs[d*64 + q] = (gq < NTOK) ? g_qkv[gq*384 +       h*32 + d] : 0.f;
        Ks[d*64 + q] = (gk < NTOK) ? g_qkv[gk*384 + 128 + h*32 + d] : 0.f;
    }
    __syncthreads();
    int ty = tid >> 4, tx = tid & 15;
    float acc[4][4] = {};
    #pragma unroll 8
    for (int d = 0; d < 32; d++) {
        float4 q4 = *(const float4*)&Qs[d*64 + ty*4];
        float4 k4 = *(const float4*)&Ks[d*64 + tx*4];
        float qv[4] = {q4.x, q4.y, q4.z, q4.w};
        float kv[4] = {k4.x, k4.y, k4.z, k4.w};
        #pragma unroll
        for (int a = 0; a < 4; a++)
            #pragma unroll
            for (int b = 0; b < 4; b++)
                acc[a][b] += qv[a] * kv[b];
    }
    const float scale = 0.17677669529663687f;   // 1/sqrt(32)
    #pragma unroll
    for (int a = 0; a < 4; a++) {
        int gq = qb + ty*4 + a;
        int gk0 = kb + tx*4;
        if (gq < NTOK && gk0 + 3 < SROW) {
            float4 st = make_float4(acc[a][0]*scale, acc[a][1]*scale,
                                    acc[a][2]*scale, acc[a][3]*scale);
            *(float4*)&g_scores[(h*NTOK + gq)*SROW + gk0] = st;
        }
    }
}

// ---------------- k4: row softmax over keys --------------------------------
__global__ void k_softmax()
{
    int rid = blockIdx.x;
    int h = rid / NTOK, q = rid % NTOK;
    int base = (h*NTOK + q) * SROW;
    int tid = threadIdx.x;        // 256
    __shared__ float redA[8], redB[8];

    float v[5]; int cnt = 0;
    float m = -1e30f;
    for (int k = tid; k < NTOK; k += 256) { float x = g_scores[base + k]; v[cnt++] = x; m = fmaxf(m, x); }
    #pragma unroll
    for (int s = 16; s; s >>= 1) m = fmaxf(m, __shfl_xor_sync(~0u, m, s));
    if ((tid & 31) == 0) redA[tid >> 5] = m;
    __syncthreads();
    m = redA[0];
    #pragma unroll
    for (int i = 1; i < 8; i++) m = fmaxf(m, redA[i]);

    float s = 0.f;
    for (int i = 0; i < cnt; i++) { v[i] = __expf(v[i] - m); s += v[i]; }
    #pragma unroll
    for (int sh = 16; sh; sh >>= 1) s += __shfl_xor_sync(~0u, s, sh);
    if ((tid & 31) == 0) redB[tid >> 5] = s;
    __syncthreads();
    float tot = 0.f;
    #pragma unroll
    for (int i = 0; i < 8; i++) tot += redB[i];
    float inv = 1.f / tot;
    int c = 0;
    for (int k = tid; k < NTOK; k += 256) g_scores[base + k] = v[c++] * inv;
}

// ---------------- k5: attn = P @ V (head-concat layout) --------------------
__global__ void k_av()
{
    __shared__ float Ps[32][64];
    __shared__ float Vs[64][32];
    int qb = blockIdx.x * 32, h = blockIdx.y;
    int tid = threadIdx.x;        // 128
    int qg = tid >> 3;            // 0..15 -> q pair
    int d0 = (tid & 7) * 4;
    float acc[2][4] = {};
    for (int kb = 0; kb < NTOK; kb += 64) {
        __syncthreads();
        for (int idx = tid; idx < 2048; idx += 128) {
            int kk = idx & 63, q = idx >> 6;
            int gq = qb + q, gk = kb + kk;
            Ps[q][kk] = (gq < NTOK && gk < NTOK) ? g_scores[(h*NTOK + gq)*SROW + gk] : 0.f;
        }
        for (int idx = tid; idx < 2048; idx += 128) {
            int dd = idx & 31, kk = idx >> 5;
            int gk = kb + kk;
            Vs[kk][dd] = (gk < NTOK) ? g_qkv[gk*384 + 256 + h*32 + dd] : 0.f;
        }
        __syncthreads();
        #pragma unroll 8
        for (int kk = 0; kk < 64; kk++) {
            float4 vv = *(const float4*)&Vs[kk][d0];
            float p0 = Ps[qg*2+0][kk];
            float p1 = Ps[qg*2+1][kk];
            acc[0][0] += p0*vv.x; acc[0][1] += p0*vv.y; acc[0][2] += p0*vv.z; acc[0][3] += p0*vv.w;
            acc[1][0] += p1*vv.x; acc[1][1] += p1*vv.y; acc[1][2] += p1*vv.z; acc[1][3] += p1*vv.w;
        }
    }
    int gq0 = qb + qg*2;
    if (gq0 < NTOK)
        *(float4*)&g_attn[gq0*HD + h*32 + d0] =
            make_float4(acc[0][0], acc[0][1], acc[0][2], acc[0][3]);
    if (gq0 + 1 < NTOK)
        *(float4*)&g_attn[(gq0+1)*HD + h*32 + d0] =
            make_float4(acc[1][0], acc[1][1], acc[1][2], acc[1][3]);
}

// -------- k6: out proj + residual + LayerNorm + FF + residual --------------
__global__ void k_post(const float* __restrict__ outw, const float* __restrict__ outb,
                       const float* __restrict__ lng,  const float* __restrict__ lnb,
                       const float* __restrict__ f1w,  const float* __restrict__ f1b,
                       const float* __restrict__ f2w,  const float* __restrict__ f2b)
{
    int r = blockIdx.x, t = threadIdx.x;   // 128 threads
    __shared__ float as_[HD], ts[HD];
    __shared__ float red[4];
    float hval = g_h[r*HD + t];
    as_[t] = g_attn[r*HD + t];
    __syncthreads();

    float o = outb[t];
    {
        const float4* w4 = (const float4*)(outw + t*HD);
        #pragma unroll 8
        for (int k4 = 0; k4 < 32; k4++) {
            float4 w = w4[k4];
            o += as_[k4*4+0]*w.x + as_[k4*4+1]*w.y + as_[k4*4+2]*w.z + as_[k4*4+3]*w.w;
        }
    }
    float x1 = hval + o;

    // mean
    float s = x1;
    #pragma unroll
    for (int sh = 16; sh; sh >>= 1) s += __shfl_xor_sync(~0u, s, sh);
    if ((t & 31) == 0) red[t >> 5] = s;
    __syncthreads();
    float mu = (red[0]+red[1]+red[2]+red[3]) * (1.f/HD);
    __syncthreads();
    // var (two-pass for stability)
    float d = x1 - mu;
    float ss = d*d;
    #pragma unroll
    for (int sh = 16; sh; sh >>= 1) ss += __shfl_xor_sync(~0u, ss, sh);
    if ((t & 31) == 0) red[t >> 5] = ss;
    __syncthreads();
    float var = (red[0]+red[1]+red[2]+red[3]) * (1.f/HD);

    float hn = d * rsqrtf(var + 1e-5f) * lng[t] + lnb[t];
    ts[t] = hn;
    __syncthreads();

    float f1 = f1b[t];
    {
        const float4* w4 = (const float4*)(f1w + t*HD);
        #pragma unroll 8
        for (int k4 = 0; k4 < 32; k4++) {
            float4 w = w4[k4];
            f1 += ts[k4*4+0]*w.x + ts[k4*4+1]*w.y + ts[k4*4+2]*w.z + ts[k4*4+3]*w.w;
        }
    }
    f1 = fmaxf(f1, 0.f);
    as_[t] = f1;
    __syncthreads();

    float f2 = f2b[t];
    {
        const float4* w4 = (const float4*)(f2w + t*HD);
        #pragma unroll 8
        for (int k4 = 0; k4 < 32; k4++) {
            float4 w = w4[k4];
            f2 += as_[k4*4+0]*w.x + as_[k4*4+1]*w.y + as_[k4*4+2]*w.z + as_[k4*4+3]*w.w;
        }
    }
    g_h2[r*HD + t] = f2 + hn;
}

// -------- k7: GRU update + c_hat -------------------------------------------
__global__ void k_gru(const float* __restrict__ memin, const int* __restrict__ pidx,
                      const float* __restrict__ wi, const float* __restrict__ wh,
                      const float* __restrict__ bi, const float* __restrict__ bh,
                      const float* __restrict__ hcw, const float* __restrict__ hcb,
                      float* __restrict__ out_c)
{
    int p = blockIdx.x, t = threadIdx.x;   // 128 threads
    __shared__ float es[HD], ps[HD];
    __shared__ float red[4];
    es[t] = g_h2[(p+1)*HD + t];
    int mi = pidx[p];
    float prev = memin[mi*HD + t];
    ps[t] = prev;
    __syncthreads();

    float gx[3], gh[3];
    #pragma unroll
    for (int g = 0; g < 3; g++) {
        float ax = bi[g*HD + t], ah = bh[g*HD + t];
        const float4* wx4 = (const float4*)(wi + (g*HD + t)*HD);
        const float4* wh4 = (const float4*)(wh + (g*HD + t)*HD);
        #pragma unroll 8
        for (int k4 = 0; k4 < 32; k4++) {
            float4 a = wx4[k4], b = wh4[k4];
            ax += es[k4*4+0]*a.x + es[k4*4+1]*a.y + es[k4*4+2]*a.z + es[k4*4+3]*a.w;
            ah += ps[k4*4+0]*b.x + ps[k4*4+1]*b.y + ps[k4*4+2]*b.z + ps[k4*4+3]*b.w;
        }
        gx[g] = ax; gh[g] = ah;
    }
    float r_ = 1.f / (1.f + __expf(-(gx[0] + gh[0])));
    float z_ = 1.f / (1.f + __expf(-(gx[1] + gh[1])));
    float n_ = tanhf(gx[2] + r_ * gh[2]);
    float m  = (1.f - z_) * n_ + z_ * prev;
    g_mem[p*HD + t] = m;

    float c = m * hcw[t];
    #pragma unroll
    for (int sh = 16; sh; sh >>= 1) c += __shfl_xor_sync(~0u, c, sh);
    if ((t & 31) == 0) red[t >> 5] = c;
    __syncthreads();
    if (t == 0) out_c[p] = red[0] + red[1] + red[2] + red[3] + hcb[0];
}

// -------- k8: hi = mem@wl.T ; hjb = mem@wr.T + e1_b ------------------------
__global__ void k_hij(const float* __restrict__ e1w, const float* __restrict__ e1b)
{
    int p = blockIdx.x, t = threadIdx.x;   // 128 threads
    __shared__ float ms[HD];
    ms[t] = g_mem[p*HD + t];
    __syncthreads();
    float hi = 0.f, hj = 0.f;
    const float4* wl4 = (const float4*)(e1w + t*256);
    const float4* wr4 = (const float4*)(e1w + t*256 + 128);
    #pragma unroll 8
    for (int k4 = 0; k4 < 32; k4++) {
        float4 a = wl4[k4], b = wr4[k4];
        hi += ms[k4*4+0]*a.x + ms[k4*4+1]*a.y + ms[k4*4+2]*a.z + ms[k4*4+3]*a.w;
        hj += ms[k4*4+0]*b.x + ms[k4*4+1]*b.y + ms[k4*4+2]*b.z + ms[k4*4+3]*b.w;
    }
    g_hi [p*HD + t] = hi;
    g_hjb[p*HD + t] = hj + e1b[t];
}

// -------- k9: pairwise head (the big one) ----------------------------------
#define HPAD 132
__global__ void k_pair(const float* __restrict__ e2w, const float* __restrict__ e2b,
                       float* __restrict__ out)
{
    __shared__ float His [32*HPAD];   // [i][d], padded vs bank conflicts
    __shared__ float HjsT[HD*32];     // [d][j]
    __shared__ float w0s[HD], w1s[HD];
    int bi = blockIdx.x * 32, bj = blockIdx.y * 32;
    int tid = threadIdx.x;            // 256
    for (int idx = tid; idx < 4096; idx += 256) {
        int i = idx >> 7, d = idx & 127;
        His[i*HPAD + d] = g_hi[(bi + i)*HD + d];
    }
    for (int idx = tid; idx < 4096; idx += 256) {
        int d = idx >> 5, j = idx & 31;
        HjsT[d*32 + j] = g_hjb[(bj + j)*HD + d];
    }
    if (tid < HD) { w0s[tid] = e2w[tid]; w1s[tid] = e2w[HD + tid]; }
    __syncthreads();

    int i  = tid >> 3;
    int j0 = (tid & 7) * 4;
    const float* hrow = &His[i*HPAD];
    float a0=0.f,a1=0.f,a2=0.f,a3=0.f;
    float b0=0.f,b1=0.f,b2=0.f,b3=0.f;
    #pragma unroll 4
    for (int d = 0; d < HD; d++) {
        float s  = hrow[d];
        float4 hj = *(const float4*)&HjsT[d*32 + j0];
        float w0 = w0s[d], w1 = w1s[d];
        float t0 = fmaxf(s + hj.x, 0.f);
        float t1 = fmaxf(s + hj.y, 0.f);
        float t2 = fmaxf(s + hj.z, 0.f);
        float t3 = fmaxf(s + hj.w, 0.f);
        a0 += t0*w0; a1 += t1*w0; a2 += t2*w0; a3 += t3*w0;
        b0 += t0*w1; b1 += t1*w1; b2 += t2*w1; b3 += t3*w1;
    }
    float eb0 = e2b[0], eb1 = e2b[1];
    float4 pv, uv;
    pv.x = 1.f/(1.f + __expf(-(a0 + eb0)));
    pv.y = 1.f/(1.f + __expf(-(a1 + eb0)));
    pv.z = 1.f/(1.f + __expf(-(a2 + eb0)));
    pv.w = 1.f/(1.f + __expf(-(a3 + eb0)));
    uv.x = fmaxf(b0 + eb1, 0.f);
    uv.y = fmaxf(b1 + eb1, 0.f);
    uv.z = fmaxf(b2 + eb1, 0.f);
    uv.w = fmaxf(b3 + eb1, 0.f);
    int gi = bi + i, gj = bj + j0;
    *(float4*)&out[1024            + gi*1024 + gj] = pv;
    *(float4*)&out[1024 + 1048576  + gi*1024 + gj] = uv;
}

// ---------------------------------------------------------------------------
extern "C" void kernel_launch(void* const* d_in, const int* in_sizes, int n_in,
                              void* d_out, int out_size)
{
    const float* env  = (const float*)d_in[0];
    const float* pf   = (const float*)d_in[1];
    const float* mw   = (const float*)d_in[2];
    const float* lc   = (const float*)d_in[3];
    const float* wal  = (const float*)d_in[4];
    const float* mem  = (const float*)d_in[5];
    const int*   pidx = (const int*)  d_in[6];
    const float* fcw  = (const float*)d_in[7];
    const float* fcb  = (const float*)d_in[8];
    const float* inw  = (const float*)d_in[9];
    const float* inb  = (const float*)d_in[10];
    const float* outw = (const float*)d_in[11];
    const float* outb = (const float*)d_in[12];
    const float* lng  = (const float*)d_in[13];
    const float* lnb  = (const float*)d_in[14];
    const float* f1w  = (const float*)d_in[15];
    const float* f1b  = (const float*)d_in[16];
    const float* f2w  = (const float*)d_in[17];
    const float* f2b  = (const float*)d_in[18];
    const float* gwi  = (const float*)d_in[19];
    const float* gwh  = (const float*)d_in[20];
    const float* gbi  = (const float*)d_in[21];
    const float* gbh  = (const float*)d_in[22];
    const float* hcw  = (const float*)d_in[23];
    const float* hcb  = (const float*)d_in[24];
    const float* e1w  = (const float*)d_in[25];
    const float* e1b  = (const float*)d_in[26];
    const float* e2w  = (const float*)d_in[27];
    const float* e2b  = (const float*)d_in[28];
    float* out = (float*)d_out;

    k_embed<<<NTOK, HD>>>(env, pf, mw, lc, wal, fcw, fcb);
    k_qkv<<<(NTOK + 7) / 8, 384>>>(inw, inb);
    {
        dim3 g((NTOK + 63) / 64, (NTOK + 63) / 64, 4);
        k_scores<<<g, 256>>>();
    }
    k_softmax<<<4 * NTOK, 256>>>();
    {
        dim3 g((NTOK + 31) / 32, 4);
        k_av<<<g, 128>>>();
    }
    k_post<<<NTOK, HD>>>(outw, outb, lng, lnb, f1w, f1b, f2w, f2b);
    k_gru<<<NPLY, HD>>>(mem, pidx, gwi, gwh, gbi, gbh, hcw, hcb, out);
    k_hij<<<NPLY, HD>>>(e1w, e1b);
    {
        dim3 g(32, 32);
        k_pair<<<g, 256>>>(e2w, e2b, out);
    }
}

// round 2
// speedup vs baseline: 1.6418x; 1.6418x over previous
#include <cuda_runtime.h>
#include <math.h>

#define NTOK 1026
#define NPLY 1024
#define HD   128

// ---------------- scratch (static device allocations only) ----------------
__device__ float g_h   [NTOK*HD];
__device__ float g_qkv [NTOK*3*HD];
__device__ float g_attn[NTOK*HD];
__device__ float g_h2  [NTOK*HD];
__device__ float g_hi  [NPLY*HD];
__device__ float g_hjb [NPLY*HD];

// ---------------- k1: build x and h = x @ fc_w.T + fc_b -------------------
__global__ void k_embed(const float* __restrict__ env, const float* __restrict__ pf,
                        const float* __restrict__ mw,  const float* __restrict__ lc,
                        const float* __restrict__ wal, const float* __restrict__ fcw,
                        const float* __restrict__ fcb)
{
    int r = blockIdx.x, o = threadIdx.x;
    const float* wrow = fcw + o * 18;
    float acc = fcb[o];
    if (r == 0) {
        #pragma unroll
        for (int t = 0; t < 16; t++) acc += wrow[2 + t] * env[t];
    } else {
        float a, b;
        if (r <= NPLY) { a = lc[r-1]; b = wal[r-1]; }
        else           { a = pf[0];   b = mw[0];    }
        acc += wrow[0]*a + wrow[1]*b;
    }
    g_h[r*HD + o] = acc;
}

// ---------------- k2: qkv = h @ in_w.T + in_b ------------------------------
__global__ void k_qkv(const float* __restrict__ inw, const float* __restrict__ inb)
{
    __shared__ float sh[8][HD];
    int rb  = blockIdx.x * 8;
    int tid = threadIdx.x;                    // 384 threads
    for (int idx = tid; idx < 8*HD; idx += 384) {
        int rr = idx >> 7, k = idx & 127;
        sh[rr][k] = (rb + rr < NTOK) ? g_h[(rb+rr)*HD + k] : 0.f;
    }
    __syncthreads();
    int o = tid;
    float acc[8];
    #pragma unroll
    for (int i = 0; i < 8; i++) acc[i] = inb[o];
    const float4* w4 = (const float4*)(inw + o * HD);
    #pragma unroll 4
    for (int k4 = 0; k4 < 32; k4++) {
        float4 w = w4[k4];
        #pragma unroll
        for (int i = 0; i < 8; i++) {
            acc[i] += sh[i][k4*4+0]*w.x + sh[i][k4*4+1]*w.y
                    + sh[i][k4*4+2]*w.z + sh[i][k4*4+3]*w.w;
        }
    }
    #pragma unroll
    for (int i = 0; i < 8; i++)
        if (rb + i < NTOK) g_qkv[(rb+i)*384 + o] = acc[i];
}

// ---------------- k3: fused flash attention (scores+softmax+AV) ------------
#define QT 16
#define KT 64
#define PPAD 68
__global__ void k_flash()
{
    __shared__ float Qs[QT*32];       // [q][d]
    __shared__ float Ks[32*KT];       // [d][k]
    __shared__ float Vs[KT*32];       // [k][d]
    __shared__ float Ps[QT*PPAD];     // [q][k] padded
    int h  = blockIdx.y;
    int qb = blockIdx.x * QT;
    int tid = threadIdx.x;            // 256
    int q  = tid >> 4;                // 0..15
    int x  = tid & 15;
    int d0 = x * 2;

    const float scale = 0.17677669529663687f;   // 1/sqrt(32)
    for (int idx = tid; idx < QT*32; idx += 256) {
        int qq = idx >> 5, d = idx & 31;
        int gq = qb + qq;
        Qs[idx] = (gq < NTOK) ? g_qkv[gq*384 + h*32 + d] * scale : 0.f;
    }

    float m = -1e30f, l = 0.f;
    float o0 = 0.f, o1 = 0.f;

    for (int kb = 0; kb < NTOK; kb += KT) {
        __syncthreads();
        for (int idx = tid; idx < 32*KT; idx += 256) {
            int k = idx & 63, d = idx >> 6;
            int gk = kb + k;
            Ks[d*KT + k] = (gk < NTOK) ? g_qkv[gk*384 + 128 + h*32 + d] : 0.f;
        }
        for (int idx = tid; idx < KT*32; idx += 256) {
            int d = idx & 31, k = idx >> 5;
            int gk = kb + k;
            Vs[k*32 + d] = (gk < NTOK) ? g_qkv[gk*384 + 256 + h*32 + d] : 0.f;
        }
        __syncthreads();

        // S tile: this thread owns row q, key cols x*4..x*4+3
        float s0 = 0.f, s1 = 0.f, s2 = 0.f, s3 = 0.f;
        const float* qrow = &Qs[q*32];
        #pragma unroll 8
        for (int d = 0; d < 32; d++) {
            float qv = qrow[d];
            float4 kv = *(const float4*)&Ks[d*KT + x*4];
            s0 += qv*kv.x; s1 += qv*kv.y; s2 += qv*kv.z; s3 += qv*kv.w;
        }
        int gk0 = kb + x*4;
        if (gk0+0 >= NTOK) s0 = -1e30f;
        if (gk0+1 >= NTOK) s1 = -1e30f;
        if (gk0+2 >= NTOK) s2 = -1e30f;
        if (gk0+3 >= NTOK) s3 = -1e30f;

        float tm = fmaxf(fmaxf(s0,s1), fmaxf(s2,s3));
        #pragma unroll
        for (int sh = 8; sh; sh >>= 1) tm = fmaxf(tm, __shfl_xor_sync(0xffffffffu, tm, sh));
        float mn = fmaxf(m, tm);
        float corr = __expf(m - mn);
        float p0 = __expf(s0 - mn), p1 = __expf(s1 - mn);
        float p2 = __expf(s2 - mn), p3 = __expf(s3 - mn);
        float ts = p0 + p1 + p2 + p3;
        #pragma unroll
        for (int sh = 8; sh; sh >>= 1) ts += __shfl_xor_sync(0xffffffffu, ts, sh);
        l = l*corr + ts;
        m = mn;
        o0 *= corr; o1 *= corr;
        *(float4*)&Ps[q*PPAD + x*4] = make_float4(p0, p1, p2, p3);
        __syncthreads();

        // AV: row q, dims d0, d0+1
        const float* prow = &Ps[q*PPAD];
        #pragma unroll 8
        for (int k = 0; k < KT; k++) {
            float p = prow[k];
            float2 vv = *(const float2*)&Vs[k*32 + d0];
            o0 += p*vv.x; o1 += p*vv.y;
        }
    }
    float inv = 1.f / l;
    int gq = qb + q;
    if (gq < NTOK) {
        g_attn[gq*HD + h*32 + d0]     = o0*inv;
        g_attn[gq*HD + h*32 + d0 + 1] = o1*inv;
    }
}

// -------- k4: out proj + residual + LN + FF + residual (8 rows/block) ------
__global__ void k_post(const float* __restrict__ outw, const float* __restrict__ outb,
                       const float* __restrict__ lng,  const float* __restrict__ lnb,
                       const float* __restrict__ f1w,  const float* __restrict__ f1b,
                       const float* __restrict__ f2w,  const float* __restrict__ f2b)
{
    int rb = blockIdx.x * 8, t = threadIdx.x;   // 128 threads
    __shared__ float as8[8][HD];
    __shared__ float ts8[8][HD];
    __shared__ float redA[8][4], redB[8][4];
    float hval[8];
    #pragma unroll
    for (int r = 0; r < 8; r++) {
        int gr = rb + r;
        as8[r][t] = (gr < NTOK) ? g_attn[gr*HD + t] : 0.f;
        hval[r]   = (gr < NTOK) ? g_h[gr*HD + t]    : 0.f;
    }
    __syncthreads();

    float acc[8];
    {
        float ob = outb[t];
        #pragma unroll
        for (int r = 0; r < 8; r++) acc[r] = ob;
        const float4* w4 = (const float4*)(outw + t*HD);
        #pragma unroll 4
        for (int k4 = 0; k4 < 32; k4++) {
            float4 w = w4[k4];
            #pragma unroll
            for (int r = 0; r < 8; r++) {
                float4 a = *(const float4*)&as8[r][k4*4];
                acc[r] += a.x*w.x + a.y*w.y + a.z*w.z + a.w*w.w;
            }
        }
    }
    float x1[8];
    #pragma unroll
    for (int r = 0; r < 8; r++) x1[r] = hval[r] + acc[r];

    // mean over t per row
    #pragma unroll
    for (int r = 0; r < 8; r++) {
        float v = x1[r];
        #pragma unroll
        for (int sh = 16; sh; sh >>= 1) v += __shfl_xor_sync(0xffffffffu, v, sh);
        if ((t & 31) == 0) redA[r][t >> 5] = v;
    }
    __syncthreads();
    float mu[8], dd[8];
    #pragma unroll
    for (int r = 0; r < 8; r++) {
        mu[r] = (redA[r][0]+redA[r][1]+redA[r][2]+redA[r][3]) * (1.f/HD);
        dd[r] = x1[r] - mu[r];
        float v = dd[r]*dd[r];
        #pragma unroll
        for (int sh = 16; sh; sh >>= 1) v += __shfl_xor_sync(0xffffffffu, v, sh);
        if ((t & 31) == 0) redB[r][t >> 5] = v;
    }
    __syncthreads();
    float hn[8];
    float g = lng[t], b = lnb[t];
    #pragma unroll
    for (int r = 0; r < 8; r++) {
        float var = (redB[r][0]+redB[r][1]+redB[r][2]+redB[r][3]) * (1.f/HD);
        hn[r] = dd[r] * rsqrtf(var + 1e-5f) * g + b;
        ts8[r][t] = hn[r];
    }
    __syncthreads();

    // ff1 + relu
    {
        float f1b_ = f1b[t];
        #pragma unroll
        for (int r = 0; r < 8; r++) acc[r] = f1b_;
        const float4* w4 = (const float4*)(f1w + t*HD);
        #pragma unroll 4
        for (int k4 = 0; k4 < 32; k4++) {
            float4 w = w4[k4];
            #pragma unroll
            for (int r = 0; r < 8; r++) {
                float4 a = *(const float4*)&ts8[r][k4*4];
                acc[r] += a.x*w.x + a.y*w.y + a.z*w.z + a.w*w.w;
            }
        }
    }
    __syncthreads();
    #pragma unroll
    for (int r = 0; r < 8; r++) as8[r][t] = fmaxf(acc[r], 0.f);
    __syncthreads();

    // ff2 + residual
    {
        float f2b_ = f2b[t];
        #pragma unroll
        for (int r = 0; r < 8; r++) acc[r] = f2b_;
        const float4* w4 = (const float4*)(f2w + t*HD);
        #pragma unroll 4
        for (int k4 = 0; k4 < 32; k4++) {
            float4 w = w4[k4];
            #pragma unroll
            for (int r = 0; r < 8; r++) {
                float4 a = *(const float4*)&as8[r][k4*4];
                acc[r] += a.x*w.x + a.y*w.y + a.z*w.z + a.w*w.w;
            }
        }
    }
    #pragma unroll
    for (int r = 0; r < 8; r++) {
        int gr = rb + r;
        if (gr < NTOK) g_h2[gr*HD + t] = acc[r] + hn[r];
    }
}

// -------- k5: GRU + c_hat + hi/hj, 8 players/block -------------------------
__global__ void k_gru(const float* __restrict__ memin, const int* __restrict__ pidx,
                      const float* __restrict__ wi, const float* __restrict__ wh,
                      const float* __restrict__ bi, const float* __restrict__ bh,
                      const float* __restrict__ hcw, const float* __restrict__ hcb,
                      const float* __restrict__ e1w, const float* __restrict__ e1b,
                      float* __restrict__ out_c)
{
    int pb = blockIdx.x * 8, t = threadIdx.x;   // 128 threads
    __shared__ float es[8][HD], ps[8][HD], ms[8][HD];
    __shared__ float redc[8][4];
    #pragma unroll
    for (int r = 0; r < 8; r++) {
        es[r][t] = g_h2[(pb + r + 1)*HD + t];
        ps[r][t] = memin[pidx[pb + r]*HD + t];
    }
    __syncthreads();

    // gates r,z: only xg+hg needed -> fuse
    float a0[8], a1[8];
    {
        float b0 = bi[t] + bh[t];
        float b1 = bi[HD + t] + bh[HD + t];
        #pragma unroll
        for (int r = 0; r < 8; r++) { a0[r] = b0; a1[r] = b1; }
        const float4* wi0 = (const float4*)(wi + t*HD);
        const float4* wh0 = (const float4*)(wh + t*HD);
        const float4* wi1 = (const float4*)(wi + (HD + t)*HD);
        const float4* wh1 = (const float4*)(wh + (HD + t)*HD);
        #pragma unroll 2
        for (int k4 = 0; k4 < 32; k4++) {
            float4 wa = wi0[k4], wb = wh0[k4], wc = wi1[k4], wd = wh1[k4];
            #pragma unroll
            for (int r = 0; r < 8; r++) {
                float4 e = *(const float4*)&es[r][k4*4];
                float4 p = *(const float4*)&ps[r][k4*4];
                a0[r] += e.x*wa.x + e.y*wa.y + e.z*wa.z + e.w*wa.w
                       + p.x*wb.x + p.y*wb.y + p.z*wb.z + p.w*wb.w;
                a1[r] += e.x*wc.x + e.y*wc.y + e.z*wc.z + e.w*wc.w
                       + p.x*wd.x + p.y*wd.y + p.z*wd.z + p.w*wd.w;
            }
        }
    }
    // gate n: xn and hn separate
    float xn[8], hg[8];
    {
        float bx = bi[2*HD + t], bhh = bh[2*HD + t];
        #pragma unroll
        for (int r = 0; r < 8; r++) { xn[r] = bx; hg[r] = bhh; }
        const float4* wi2 = (const float4*)(wi + (2*HD + t)*HD);
        const float4* wh2 = (const float4*)(wh + (2*HD + t)*HD);
        #pragma unroll 2
        for (int k4 = 0; k4 < 32; k4++) {
            float4 wa = wi2[k4], wb = wh2[k4];
            #pragma unroll
            for (int r = 0; r < 8; r++) {
                float4 e = *(const float4*)&es[r][k4*4];
                float4 p = *(const float4*)&ps[r][k4*4];
                xn[r] += e.x*wa.x + e.y*wa.y + e.z*wa.z + e.w*wa.w;
                hg[r] += p.x*wb.x + p.y*wb.y + p.z*wb.z + p.w*wb.w;
            }
        }
    }
    float hcwt = hcw[t];
    #pragma unroll
    for (int r = 0; r < 8; r++) {
        float rr = 1.f / (1.f + __expf(-a0[r]));
        float zz = 1.f / (1.f + __expf(-a1[r]));
        float nn = tanhf(xn[r] + rr * hg[r]);
        float mv = (1.f - zz) * nn + zz * ps[r][t];
        ms[r][t] = mv;
        float c = mv * hcwt;
        #pragma unroll
        for (int sh = 16; sh; sh >>= 1) c += __shfl_xor_sync(0xffffffffu, c, sh);
        if ((t & 31) == 0) redc[r][t >> 5] = c;
    }
    __syncthreads();
    if (t < 8)
        out_c[pb + t] = redc[t][0] + redc[t][1] + redc[t][2] + redc[t][3] + hcb[0];

    // hi / hj from ms
    float hi[8], hj[8];
    #pragma unroll
    for (int r = 0; r < 8; r++) { hi[r] = 0.f; hj[r] = 0.f; }
    const float4* wl4 = (const float4*)(e1w + t*256);
    const float4* wr4 = (const float4*)(e1w + t*256 + 128);
    #pragma unroll 2
    for (int k4 = 0; k4 < 32; k4++) {
        float4 a = wl4[k4], b = wr4[k4];
        #pragma unroll
        for (int r = 0; r < 8; r++) {
            float4 mv = *(const float4*)&ms[r][k4*4];
            hi[r] += mv.x*a.x + mv.y*a.y + mv.z*a.z + mv.w*a.w;
            hj[r] += mv.x*b.x + mv.y*b.y + mv.z*b.z + mv.w*b.w;
        }
    }
    float eb = e1b[t];
    #pragma unroll
    for (int r = 0; r < 8; r++) {
        g_hi [(pb + r)*HD + t] = hi[r];
        g_hjb[(pb + r)*HD + t] = hj[r] + eb;
    }
}

// -------- k6: pairwise head (the big one) ----------------------------------
#define HPAD 132
__global__ void k_pair(const float* __restrict__ e2w, const float* __restrict__ e2b,
                       float* __restrict__ out)
{
    __shared__ float His [32*HPAD];   // [i][d], padded vs bank conflicts
    __shared__ float HjsT[HD*32];     // [d][j]
    __shared__ float w0s[HD], w1s[HD];
    int bi = blockIdx.x * 32, bj = blockIdx.y * 32;
    int tid = threadIdx.x;            // 256
    for (int idx = tid; idx < 4096; idx += 256) {
        int i = idx >> 7, d = idx & 127;
        His[i*HPAD + d] = g_hi[(bi + i)*HD + d];
    }
    for (int idx = tid; idx < 4096; idx += 256) {
        int d = idx >> 5, j = idx & 31;
        HjsT[d*32 + j] = g_hjb[(bj + j)*HD + d];
    }
    if (tid < HD) { w0s[tid] = e2w[tid]; w1s[tid] = e2w[HD + tid]; }
    __syncthreads();

    int i  = tid >> 3;
    int j0 = (tid & 7) * 4;
    const float* hrow = &His[i*HPAD];
    float a0=0.f,a1=0.f,a2=0.f,a3=0.f;
    float b0=0.f,b1=0.f,b2=0.f,b3=0.f;
    #pragma unroll 4
    for (int d = 0; d < HD; d++) {
        float s  = hrow[d];
        float4 hj = *(const float4*)&HjsT[d*32 + j0];
        float w0 = w0s[d], w1 = w1s[d];
        float t0 = fmaxf(s + hj.x, 0.f);
        float t1 = fmaxf(s + hj.y, 0.f);
        float t2 = fmaxf(s + hj.z, 0.f);
        float t3 = fmaxf(s + hj.w, 0.f);
        a0 += t0*w0; a1 += t1*w0; a2 += t2*w0; a3 += t3*w0;
        b0 += t0*w1; b1 += t1*w1; b2 += t2*w1; b3 += t3*w1;
    }
    float eb0 = e2b[0], eb1 = e2b[1];
    float4 pv, uv;
    pv.x = 1.f/(1.f + __expf(-(a0 + eb0)));
    pv.y = 1.f/(1.f + __expf(-(a1 + eb0)));
    pv.z = 1.f/(1.f + __expf(-(a2 + eb0)));
    pv.w = 1.f/(1.f + __expf(-(a3 + eb0)));
    uv.x = fmaxf(b0 + eb1, 0.f);
    uv.y = fmaxf(b1 + eb1, 0.f);
    uv.z = fmaxf(b2 + eb1, 0.f);
    uv.w = fmaxf(b3 + eb1, 0.f);
    int gi = bi + i, gj = bj + j0;
    *(float4*)&out[1024            + gi*1024 + gj] = pv;
    *(float4*)&out[1024 + 1048576  + gi*1024 + gj] = uv;
}

// ---------------------------------------------------------------------------
extern "C" void kernel_launch(void* const* d_in, const int* in_sizes, int n_in,
                              void* d_out, int out_size)
{
    const float* env  = (const float*)d_in[0];
    const float* pf   = (const float*)d_in[1];
    const float* mw   = (const float*)d_in[2];
    const float* lc   = (const float*)d_in[3];
    const float* wal  = (const float*)d_in[4];
    const float* mem  = (const float*)d_in[5];
    const int*   pidx = (const int*)  d_in[6];
    const float* fcw  = (const float*)d_in[7];
    const float* fcb  = (const float*)d_in[8];
    const float* inw  = (const float*)d_in[9];
    const float* inb  = (const float*)d_in[10];
    const float* outw = (const float*)d_in[11];
    const float* outb = (const float*)d_in[12];
    const float* lng  = (const float*)d_in[13];
    const float* lnb  = (const float*)d_in[14];
    const float* f1w  = (const float*)d_in[15];
    const float* f1b  = (const float*)d_in[16];
    const float* f2w  = (const float*)d_in[17];
    const float* f2b  = (const float*)d_in[18];
    const float* gwi  = (const float*)d_in[19];
    const float* gwh  = (const float*)d_in[20];
    const float* gbi  = (const float*)d_in[21];
    const float* gbh  = (const float*)d_in[22];
    const float* hcw  = (const float*)d_in[23];
    const float* hcb  = (const float*)d_in[24];
    const float* e1w  = (const float*)d_in[25];
    const float* e1b  = (const float*)d_in[26];
    const float* e2w  = (const float*)d_in[27];
    const float* e2b  = (const float*)d_in[28];
    float* out = (float*)d_out;

    k_embed<<<NTOK, HD>>>(env, pf, mw, lc, wal, fcw, fcb);
    k_qkv<<<(NTOK + 7) / 8, 384>>>(inw, inb);
    {
        dim3 g((NTOK + QT - 1) / QT, 4);
        k_flash<<<g, 256>>>();
    }
    k_post<<<(NTOK + 7) / 8, 128>>>(outw, outb, lng, lnb, f1w, f1b, f2w, f2b);
    k_gru<<<NPLY / 8, 128>>>(mem, pidx, gwi, gwh, gbi, gbh, hcw, hcb, e1w, e1b, out);
    {
        dim3 g(32, 32);
        k_pair<<<g, 256>>>(e2w, e2b, out);
    }
}